// round 3
// baseline (speedup 1.0000x reference)
#include <cuda_runtime.h>
#include <cstdint>

#define N_NODES 100000
#define E_EDGES 1600000
#define D_IN   64
#define D_HID  64
#define D_OUT  40
#define BN_EPS 1e-5f

// ---------------- scratch (no allocations allowed; float4 => 16B aligned) ----
__device__ float4 g_agg1[(size_t)N_NODES * D_IN / 4];
__device__ float4 g_h[(size_t)N_NODES * D_HID / 4];
__device__ float4 g_agg2[(size_t)N_NODES * D_HID / 4];
__device__ float  g_invcnt[N_NODES];
__device__ int    g_cnt[N_NODES];
__device__ float  g_sum[D_HID];
__device__ float  g_sumsq[D_HID];
__device__ float  g_scale[D_HID];
__device__ float  g_shift[D_HID];

// ---------------- weights in constant memory (uniform access -> LDCU) ----
__constant__ float4 c_W1l[D_HID * D_IN / 4];   // [64][16] float4
__constant__ float4 c_W1r[D_HID * D_IN / 4];
__constant__ float  c_b1[D_HID];
__constant__ float4 c_W2l[D_OUT * D_HID / 4];  // [40][16] float4
__constant__ float4 c_W2r[D_OUT * D_HID / 4];
__constant__ float  c_b2[D_OUT];

// ---------------- kernels ----------------
__global__ void k_zero() {
    int i = blockIdx.x * blockDim.x + threadIdx.x;
    int stride = gridDim.x * blockDim.x;
    float4 z = make_float4(0.f, 0.f, 0.f, 0.f);
    int total4 = N_NODES * (D_IN / 4);  // 1.6M float4 per array
    for (int t = i; t < total4; t += stride) {
        g_agg1[t] = z;
        g_agg2[t] = z;
    }
    for (int t = i; t < N_NODES; t += stride) g_cnt[t] = 0;
    if (i < D_HID) { g_sum[i] = 0.f; g_sumsq[i] = 0.f; }
}

__global__ void k_count(const int* __restrict__ dst) {
    int e = blockIdx.x * blockDim.x + threadIdx.x;
    if (e < E_EDGES) atomicAdd(&g_cnt[dst[e]], 1);
}

__global__ void k_invcnt() {
    int i = blockIdx.x * blockDim.x + threadIdx.x;
    if (i < N_NODES) {
        int c = g_cnt[i];
        g_invcnt[i] = 1.0f / (float)(c > 0 ? c : 1);
    }
}

// One warp handles 2 edges: 16 lanes/edge, one float4 per lane (64 floats).
__device__ __forceinline__ void scatter_body(const float4* __restrict__ feat,
                                             float4* __restrict__ out,
                                             const int* __restrict__ src,
                                             const int* __restrict__ dst) {
    int gw = (blockIdx.x * blockDim.x + threadIdx.x) >> 5;  // global warp
    int lane = threadIdx.x & 31;
    int sub = lane >> 4;   // 0..1 : which edge within warp
    int q   = lane & 15;   // float4 index within the 64-float row
    long long e = (long long)gw * 2 + sub;
    if (e >= E_EDGES) return;
    int s = src[e];
    int d = dst[e];
    float4 v = feat[(size_t)s * 16 + q];
    float4* p = out + (size_t)d * 16 + q;
    asm volatile("red.global.add.v4.f32 [%0], {%1,%2,%3,%4};"
                 :: "l"(p), "f"(v.x), "f"(v.y), "f"(v.z), "f"(v.w)
                 : "memory");
}

__global__ void k_scatter1(const float4* __restrict__ x,
                           const int* __restrict__ src,
                           const int* __restrict__ dst) {
    scatter_body(x, g_agg1, src, dst);
}

__global__ void k_scatter2(const int* __restrict__ src,
                           const int* __restrict__ dst) {
    scatter_body(g_h, g_agg2, src, dst);
}

// Layer 1: h_pre[n][j] = b1[j] + sum_k W1l[j][k]*agg1[n][k]*invcnt[n] + W1r[j][k]*x[n][k]
__global__ __launch_bounds__(128) void k_gemm1(const float4* __restrict__ x) {
    int n = blockIdx.x * 128 + threadIdx.x;
    if (n >= N_NODES) return;
    float ic = g_invcnt[n];
    float4 xv[16], av[16];
    const float4* xp = x + (size_t)n * 16;
    const float4* ap = g_agg1 + (size_t)n * 16;
#pragma unroll
    for (int c = 0; c < 16; c++) {
        xv[c] = xp[c];
        float4 a = ap[c];
        av[c] = make_float4(a.x * ic, a.y * ic, a.z * ic, a.w * ic);
    }
    float* hp = reinterpret_cast<float*>(g_h) + (size_t)n * D_HID;
#pragma unroll 1
    for (int j = 0; j < D_HID; j++) {
        float acc0 = c_b1[j];
        float acc1 = 0.f;
#pragma unroll
        for (int c = 0; c < 8; c++) {
            float4 wl = c_W1l[j * 16 + c];
            float4 wr = c_W1r[j * 16 + c];
            acc0 += wl.x * av[c].x + wl.y * av[c].y + wl.z * av[c].z + wl.w * av[c].w;
            acc0 += wr.x * xv[c].x + wr.y * xv[c].y + wr.z * xv[c].z + wr.w * xv[c].w;
        }
#pragma unroll
        for (int c = 8; c < 16; c++) {
            float4 wl = c_W1l[j * 16 + c];
            float4 wr = c_W1r[j * 16 + c];
            acc1 += wl.x * av[c].x + wl.y * av[c].y + wl.z * av[c].z + wl.w * av[c].w;
            acc1 += wr.x * xv[c].x + wr.y * xv[c].y + wr.z * xv[c].z + wr.w * xv[c].w;
        }
        hp[j] = acc0 + acc1;
    }
}

// Column sums of h and h^2 (for BatchNorm batch statistics).
#define STATS_ROWS 256
__global__ void k_colstats() {
    __shared__ float ssum[256];
    __shared__ float ssq[256];
    const float* h = reinterpret_cast<const float*>(g_h);
    int j = threadIdx.x & 63;
    int rs = threadIdx.x >> 6;  // 0..3
    int row0 = blockIdx.x * STATS_ROWS;
    float s = 0.f, q = 0.f;
    int rend = row0 + STATS_ROWS;
    if (rend > N_NODES) rend = N_NODES;
    for (int r = row0 + rs; r < rend; r += 4) {
        float v = h[(size_t)r * D_HID + j];
        s += v;
        q += v * v;
    }
    ssum[threadIdx.x] = s;
    ssq[threadIdx.x] = q;
    __syncthreads();
    if (rs == 0) {
        float ts = ssum[j] + ssum[64 + j] + ssum[128 + j] + ssum[192 + j];
        float tq = ssq[j] + ssq[64 + j] + ssq[128 + j] + ssq[192 + j];
        atomicAdd(&g_sum[j], ts);
        atomicAdd(&g_sumsq[j], tq);
    }
}

__global__ void k_bnfin(const float* __restrict__ gamma, const float* __restrict__ beta) {
    int j = threadIdx.x;
    if (j < D_HID) {
        float mu = g_sum[j] * (1.0f / (float)N_NODES);
        float var = g_sumsq[j] * (1.0f / (float)N_NODES) - mu * mu;
        float rs = rsqrtf(var + BN_EPS);
        float sc = gamma[j] * rs;
        g_scale[j] = sc;
        g_shift[j] = beta[j] - mu * sc;
    }
}

__global__ void k_bnrelu() {
    int i = blockIdx.x * blockDim.x + threadIdx.x;
    int stride = gridDim.x * blockDim.x;
    int total4 = N_NODES * 16;
    for (int t = i; t < total4; t += stride) {
        int c = t & 15;
        float4 sc = reinterpret_cast<const float4*>(g_scale)[c];
        float4 sh = reinterpret_cast<const float4*>(g_shift)[c];
        float4 h = g_h[t];
        h.x = fmaxf(fmaf(h.x, sc.x, sh.x), 0.f);
        h.y = fmaxf(fmaf(h.y, sc.y, sh.y), 0.f);
        h.z = fmaxf(fmaf(h.z, sc.z, sh.z), 0.f);
        h.w = fmaxf(fmaf(h.w, sc.w, sh.w), 0.f);
        g_h[t] = h;
    }
}

// Layer 2: out[n][j] = b2[j] + sum_k W2l[j][k]*agg2[n][k]*invcnt[n] + W2r[j][k]*h[n][k]
__global__ __launch_bounds__(128) void k_gemm2(float* __restrict__ out) {
    int n = blockIdx.x * 128 + threadIdx.x;
    if (n >= N_NODES) return;
    float ic = g_invcnt[n];
    float4 hv[16], av[16];
    const float4* hp = g_h + (size_t)n * 16;
    const float4* ap = g_agg2 + (size_t)n * 16;
#pragma unroll
    for (int c = 0; c < 16; c++) {
        hv[c] = hp[c];
        float4 a = ap[c];
        av[c] = make_float4(a.x * ic, a.y * ic, a.z * ic, a.w * ic);
    }
    float* op = out + (size_t)n * D_OUT;
#pragma unroll 1
    for (int j = 0; j < D_OUT; j++) {
        float acc0 = c_b2[j];
        float acc1 = 0.f;
#pragma unroll
        for (int c = 0; c < 8; c++) {
            float4 wl = c_W2l[j * 16 + c];
            float4 wr = c_W2r[j * 16 + c];
            acc0 += wl.x * av[c].x + wl.y * av[c].y + wl.z * av[c].z + wl.w * av[c].w;
            acc0 += wr.x * hv[c].x + wr.y * hv[c].y + wr.z * hv[c].z + wr.w * hv[c].w;
        }
#pragma unroll
        for (int c = 8; c < 16; c++) {
            float4 wl = c_W2l[j * 16 + c];
            float4 wr = c_W2r[j * 16 + c];
            acc1 += wl.x * av[c].x + wl.y * av[c].y + wl.z * av[c].z + wl.w * av[c].w;
            acc1 += wr.x * hv[c].x + wr.y * hv[c].y + wr.z * hv[c].z + wr.w * hv[c].w;
        }
        op[j] = acc0 + acc1;
    }
}

// ---------------- launch ----------------
extern "C" void kernel_launch(void* const* d_in, const int* in_sizes, int n_in,
                              void* d_out, int out_size) {
    const float4* x     = (const float4*)d_in[0];
    const int*    ei    = (const int*)d_in[1];    // jax x64 disabled -> int32
    const float*  gamma = (const float*)d_in[5];
    const float*  beta  = (const float*)d_in[6];
    const int* src = ei;
    const int* dst = ei + E_EDGES;
    float* out = (float*)d_out;

    // Stage weights into constant memory (device-to-device async copies: capturable)
    cudaMemcpyToSymbolAsync(c_W1l, d_in[2], D_HID * D_IN * sizeof(float), 0, cudaMemcpyDeviceToDevice, 0);
    cudaMemcpyToSymbolAsync(c_W1r, d_in[3], D_HID * D_IN * sizeof(float), 0, cudaMemcpyDeviceToDevice, 0);
    cudaMemcpyToSymbolAsync(c_b1,  d_in[4], D_HID * sizeof(float),        0, cudaMemcpyDeviceToDevice, 0);
    cudaMemcpyToSymbolAsync(c_W2l, d_in[7], D_OUT * D_HID * sizeof(float), 0, cudaMemcpyDeviceToDevice, 0);
    cudaMemcpyToSymbolAsync(c_W2r, d_in[8], D_OUT * D_HID * sizeof(float), 0, cudaMemcpyDeviceToDevice, 0);
    cudaMemcpyToSymbolAsync(c_b2,  d_in[9], D_OUT * sizeof(float),         0, cudaMemcpyDeviceToDevice, 0);

    k_zero<<<1024, 256>>>();
    k_count<<<(E_EDGES + 255) / 256, 256>>>(dst);
    k_invcnt<<<(N_NODES + 255) / 256, 256>>>();

    // scatter-mean layer 1: 2 edges per warp -> E/16 edges per 256-thread block
    k_scatter1<<<E_EDGES / 16, 256>>>(x, src, dst);
    k_gemm1<<<(N_NODES + 127) / 128, 128>>>(x);

    k_colstats<<<(N_NODES + STATS_ROWS - 1) / STATS_ROWS, 256>>>();
    k_bnfin<<<1, 64>>>(gamma, beta);
    k_bnrelu<<<2048, 256>>>();

    // scatter-mean layer 2
    k_scatter2<<<E_EDGES / 16, 256>>>(src, dst);
    k_gemm2<<<(N_NODES + 127) / 128, 128>>>(out);
}

// round 4
// speedup vs baseline: 1.2008x; 1.2008x over previous
#include <cuda_runtime.h>
#include <cstdint>

#define N_NODES 100000
#define E_EDGES 1600000
#define D_IN   64
#define D_HID  64
#define D_OUT  40
#define BN_EPS 1e-5f

// ---------------- scratch (float4 => 16B aligned) ----------------
__device__ float4 g_agg1[(size_t)N_NODES * 16];   // mean of neighbor x, pre-divided
__device__ float4 g_h[(size_t)N_NODES * 16];      // layer-1 output / normalized h
__device__ float4 g_p[(size_t)N_NODES * 10];      // h @ W2l.T  (40-dim)
__device__ float4 g_agg2[(size_t)N_NODES * 10];   // mean of neighbor p, pre-divided
__device__ int    g_adj[E_EDGES];                 // CSR adjacency (src ids grouped by dst)
__device__ int    g_cnt[N_NODES];
__device__ int    g_rowstart[N_NODES];
__device__ int    g_cursor[N_NODES];
__device__ int    g_total;
__device__ float  g_sum[D_HID];
__device__ float  g_sumsq[D_HID];
__device__ float  g_scale[D_HID];
__device__ float  g_shift[D_HID];

// ---------------- weights in constant memory ----------------
__constant__ float4 c_W1l[D_HID * D_IN / 4];
__constant__ float4 c_W1r[D_HID * D_IN / 4];
__constant__ float  c_b1[D_HID];
__constant__ float4 c_W2l[D_OUT * D_HID / 4];
__constant__ float4 c_W2r[D_OUT * D_HID / 4];
__constant__ float  c_b2[D_OUT];

// ---------------- CSR construction ----------------
__global__ void k_zero() {
    int i = blockIdx.x * blockDim.x + threadIdx.x;
    int stride = gridDim.x * blockDim.x;
    for (int t = i; t < N_NODES; t += stride) g_cnt[t] = 0;
    if (i < D_HID) { g_sum[i] = 0.f; g_sumsq[i] = 0.f; }
    if (i == 0) g_total = 0;
}

__global__ void k_count(const int* __restrict__ dst) {
    int e = blockIdx.x * blockDim.x + threadIdx.x;
    if (e < E_EDGES) atomicAdd(&g_cnt[dst[e]], 1);
}

// Warp-aggregated slot allocation: per-warp inclusive scan of counts, one
// global atomicAdd per warp. Slot ranges are disjoint; global order arbitrary.
__global__ void k_alloc() {
    int n = blockIdx.x * blockDim.x + threadIdx.x;
    int lane = threadIdx.x & 31;
    int cnt = (n < N_NODES) ? g_cnt[n] : 0;
    int incl = cnt;
#pragma unroll
    for (int o = 1; o < 32; o <<= 1) {
        int v = __shfl_up_sync(0xffffffffu, incl, o);
        if (lane >= o) incl += v;
    }
    int base = 0;
    if (lane == 31) base = atomicAdd(&g_total, incl);
    base = __shfl_sync(0xffffffffu, base, 31);
    if (n < N_NODES) {
        int rs = base + incl - cnt;
        g_rowstart[n] = rs;
        g_cursor[n] = rs;
    }
}

__global__ void k_fill(const int* __restrict__ src, const int* __restrict__ dst) {
    int e = blockIdx.x * blockDim.x + threadIdx.x;
    if (e < E_EDGES) {
        int d = dst[e];
        int pos = atomicAdd(&g_cursor[d], 1);
        g_adj[pos] = src[e];
    }
}

// ---------------- aggregation (gather, register accumulate) ----------------
// Layer 1: warp = 2 nodes, 16 lanes each hold one float4 of the 64-float row.
__global__ __launch_bounds__(256) void k_agg1(const float4* __restrict__ x) {
    int gw = (blockIdx.x * blockDim.x + threadIdx.x) >> 5;
    int lane = threadIdx.x & 31;
    int sub = lane >> 4;
    int q = lane & 15;
    int n = gw * 2 + sub;
    if (n >= N_NODES) return;
    int beg = g_rowstart[n];
    int cnt = g_cnt[n];
    float4 acc = make_float4(0.f, 0.f, 0.f, 0.f);
    int s_next = (cnt > 0) ? g_adj[beg] : 0;
    for (int i = 0; i < cnt; i++) {
        int s = s_next;
        s_next = (i + 1 < cnt) ? g_adj[beg + i + 1] : 0;
        float4 v = x[(size_t)s * 16 + q];
        acc.x += v.x; acc.y += v.y; acc.z += v.z; acc.w += v.w;
    }
    float inv = 1.0f / (float)(cnt > 0 ? cnt : 1);
    acc.x *= inv; acc.y *= inv; acc.z *= inv; acc.w *= inv;
    g_agg1[(size_t)n * 16 + q] = acc;
}

// Layer 2 on projected p (40 floats = 10 float4): warp = 3 nodes, 10 lanes each.
__global__ __launch_bounds__(256) void k_agg2() {
    int gw = (blockIdx.x * blockDim.x + threadIdx.x) >> 5;
    int lane = threadIdx.x & 31;
    int sub = lane / 10;          // 0..2 active, sub==3 (lanes 30,31) idle
    int q = lane - sub * 10;
    int n = gw * 3 + sub;
    if (sub >= 3 || n >= N_NODES) return;
    int beg = g_rowstart[n];
    int cnt = g_cnt[n];
    float4 acc = make_float4(0.f, 0.f, 0.f, 0.f);
    int s_next = (cnt > 0) ? g_adj[beg] : 0;
    for (int i = 0; i < cnt; i++) {
        int s = s_next;
        s_next = (i + 1 < cnt) ? g_adj[beg + i + 1] : 0;
        float4 v = g_p[(size_t)s * 10 + q];
        acc.x += v.x; acc.y += v.y; acc.z += v.z; acc.w += v.w;
    }
    float inv = 1.0f / (float)(cnt > 0 ? cnt : 1);
    acc.x *= inv; acc.y *= inv; acc.z *= inv; acc.w *= inv;
    g_agg2[(size_t)n * 10 + q] = acc;
}

// ---------------- layer 1 GEMM ----------------
// h_pre[n][j] = b1[j] + W1l[j]·agg1[n] + W1r[j]·x[n]
__global__ __launch_bounds__(128) void k_gemm1(const float4* __restrict__ x) {
    int n = blockIdx.x * 128 + threadIdx.x;
    if (n >= N_NODES) return;
    float4 xv[16], av[16];
    const float4* xp = x + (size_t)n * 16;
    const float4* ap = g_agg1 + (size_t)n * 16;
#pragma unroll
    for (int c = 0; c < 16; c++) { xv[c] = xp[c]; av[c] = ap[c]; }
    float* hp = reinterpret_cast<float*>(g_h) + (size_t)n * D_HID;
#pragma unroll 1
    for (int j = 0; j < D_HID; j++) {
        float acc0 = c_b1[j];
        float acc1 = 0.f;
#pragma unroll
        for (int c = 0; c < 8; c++) {
            float4 wl = c_W1l[j * 16 + c];
            float4 wr = c_W1r[j * 16 + c];
            acc0 += wl.x * av[c].x + wl.y * av[c].y + wl.z * av[c].z + wl.w * av[c].w;
            acc0 += wr.x * xv[c].x + wr.y * xv[c].y + wr.z * xv[c].z + wr.w * xv[c].w;
        }
#pragma unroll
        for (int c = 8; c < 16; c++) {
            float4 wl = c_W1l[j * 16 + c];
            float4 wr = c_W1r[j * 16 + c];
            acc1 += wl.x * av[c].x + wl.y * av[c].y + wl.z * av[c].z + wl.w * av[c].w;
            acc1 += wr.x * xv[c].x + wr.y * xv[c].y + wr.z * xv[c].z + wr.w * xv[c].w;
        }
        hp[j] = acc0 + acc1;
    }
}

// ---------------- BN stats ----------------
#define STATS_ROWS 256
__global__ void k_colstats() {
    __shared__ float ssum[256];
    __shared__ float ssq[256];
    const float* h = reinterpret_cast<const float*>(g_h);
    int j = threadIdx.x & 63;
    int rs = threadIdx.x >> 6;
    int row0 = blockIdx.x * STATS_ROWS;
    float s = 0.f, q = 0.f;
    int rend = row0 + STATS_ROWS;
    if (rend > N_NODES) rend = N_NODES;
    for (int r = row0 + rs; r < rend; r += 4) {
        float v = h[(size_t)r * D_HID + j];
        s += v;
        q += v * v;
    }
    ssum[threadIdx.x] = s;
    ssq[threadIdx.x] = q;
    __syncthreads();
    if (rs == 0) {
        atomicAdd(&g_sum[j], ssum[j] + ssum[64 + j] + ssum[128 + j] + ssum[192 + j]);
        atomicAdd(&g_sumsq[j], ssq[j] + ssq[64 + j] + ssq[128 + j] + ssq[192 + j]);
    }
}

__global__ void k_bnfin(const float* __restrict__ gamma, const float* __restrict__ beta) {
    int j = threadIdx.x;
    if (j < D_HID) {
        float mu = g_sum[j] * (1.0f / (float)N_NODES);
        float var = g_sumsq[j] * (1.0f / (float)N_NODES) - mu * mu;
        float rs = rsqrtf(var + BN_EPS);
        float sc = gamma[j] * rs;
        g_scale[j] = sc;
        g_shift[j] = beta[j] - mu * sc;
    }
}

// ---------------- BN + ReLU + projection p = h @ W2l.T ----------------
__global__ __launch_bounds__(128) void k_bnrelu_proj() {
    int n = blockIdx.x * 128 + threadIdx.x;
    if (n >= N_NODES) return;
    float4 hv[16];
    float4* hp = g_h + (size_t)n * 16;
#pragma unroll
    for (int c = 0; c < 16; c++) {
        float4 sc = reinterpret_cast<const float4*>(g_scale)[c];
        float4 sh = reinterpret_cast<const float4*>(g_shift)[c];
        float4 h = hp[c];
        h.x = fmaxf(fmaf(h.x, sc.x, sh.x), 0.f);
        h.y = fmaxf(fmaf(h.y, sc.y, sh.y), 0.f);
        h.z = fmaxf(fmaf(h.z, sc.z, sh.z), 0.f);
        h.w = fmaxf(fmaf(h.w, sc.w, sh.w), 0.f);
        hv[c] = h;
        hp[c] = h;
    }
    float4* pp = g_p + (size_t)n * 10;
    float pj[4];
#pragma unroll 1
    for (int jb = 0; jb < 10; jb++) {
#pragma unroll
        for (int u = 0; u < 4; u++) {
            int j = jb * 4 + u;
            float acc = 0.f;
#pragma unroll
            for (int c = 0; c < 16; c++) {
                float4 wl = c_W2l[j * 16 + c];
                acc += wl.x * hv[c].x + wl.y * hv[c].y + wl.z * hv[c].z + wl.w * hv[c].w;
            }
            pj[u] = acc;
        }
        pp[jb] = make_float4(pj[0], pj[1], pj[2], pj[3]);
    }
}

// ---------------- final: out = agg2 + h @ W2r.T + b2 ----------------
__global__ __launch_bounds__(128) void k_gemm2f(float4* __restrict__ out) {
    int n = blockIdx.x * 128 + threadIdx.x;
    if (n >= N_NODES) return;
    float4 hv[16];
    const float4* hp = g_h + (size_t)n * 16;
#pragma unroll
    for (int c = 0; c < 16; c++) hv[c] = hp[c];
    const float4* ap = g_agg2 + (size_t)n * 10;
    float4* op = out + (size_t)n * 10;
    float oj[4];
#pragma unroll 1
    for (int jb = 0; jb < 10; jb++) {
        float4 a = ap[jb];
#pragma unroll
        for (int u = 0; u < 4; u++) {
            int j = jb * 4 + u;
            float acc = c_b2[j];
#pragma unroll
            for (int c = 0; c < 16; c++) {
                float4 wr = c_W2r[j * 16 + c];
                acc += wr.x * hv[c].x + wr.y * hv[c].y + wr.z * hv[c].z + wr.w * hv[c].w;
            }
            oj[u] = acc;
        }
        op[jb] = make_float4(oj[0] + a.x, oj[1] + a.y, oj[2] + a.z, oj[3] + a.w);
    }
}

// ---------------- launch ----------------
extern "C" void kernel_launch(void* const* d_in, const int* in_sizes, int n_in,
                              void* d_out, int out_size) {
    const float4* x     = (const float4*)d_in[0];
    const int*    ei    = (const int*)d_in[1];   // int32 (jax x64 disabled)
    const float*  gamma = (const float*)d_in[5];
    const float*  beta  = (const float*)d_in[6];
    const int* src = ei;
    const int* dst = ei + E_EDGES;

    cudaMemcpyToSymbolAsync(c_W1l, d_in[2], D_HID * D_IN * sizeof(float), 0, cudaMemcpyDeviceToDevice, 0);
    cudaMemcpyToSymbolAsync(c_W1r, d_in[3], D_HID * D_IN * sizeof(float), 0, cudaMemcpyDeviceToDevice, 0);
    cudaMemcpyToSymbolAsync(c_b1,  d_in[4], D_HID * sizeof(float),        0, cudaMemcpyDeviceToDevice, 0);
    cudaMemcpyToSymbolAsync(c_W2l, d_in[7], D_OUT * D_HID * sizeof(float), 0, cudaMemcpyDeviceToDevice, 0);
    cudaMemcpyToSymbolAsync(c_W2r, d_in[8], D_OUT * D_HID * sizeof(float), 0, cudaMemcpyDeviceToDevice, 0);
    cudaMemcpyToSymbolAsync(c_b2,  d_in[9], D_OUT * sizeof(float),         0, cudaMemcpyDeviceToDevice, 0);

    // CSR build (shared by both layers)
    k_zero<<<256, 256>>>();
    k_count<<<(E_EDGES + 255) / 256, 256>>>(dst);
    k_alloc<<<(N_NODES + 127) / 128, 128>>>();
    k_fill<<<(E_EDGES + 255) / 256, 256>>>(src, dst);

    // Layer 1
    k_agg1<<<(N_NODES / 2 + 7) / 8, 256>>>(x);           // 2 nodes/warp, 8 warps/block
    k_gemm1<<<(N_NODES + 127) / 128, 128>>>(x);

    // BatchNorm + ReLU + layer-2 left-projection
    k_colstats<<<(N_NODES + STATS_ROWS - 1) / STATS_ROWS, 256>>>();
    k_bnfin<<<1, 64>>>(gamma, beta);
    k_bnrelu_proj<<<(N_NODES + 127) / 128, 128>>>();

    // Layer 2
    k_agg2<<<(N_NODES / 3 + 8) / 8, 256>>>();            // 3 nodes/warp, 8 warps/block
    k_gemm2f<<<(N_NODES + 127) / 128, 128>>>((float4*)d_out);
}

// round 5
// speedup vs baseline: 1.3422x; 1.1177x over previous
#include <cuda_runtime.h>
#include <cstdint>

#define N_NODES 100000
#define E_EDGES 1600000
#define D_IN   64
#define D_HID  64
#define D_OUT  40
#define BN_EPS 1e-5f

// ---------------- scratch (float4 => 16B aligned) ----------------
__device__ float4 g_agg1[(size_t)N_NODES * 16];   // mean of neighbor x
__device__ float4 g_h[(size_t)N_NODES * 16];      // layer-1 pre-BN output
__device__ float4 g_p[(size_t)N_NODES * 10];      // relu(bn(h)) @ W2l.T
__device__ int    g_adj[E_EDGES];
__device__ int    g_cnt[N_NODES];
__device__ int    g_rowstart[N_NODES];
__device__ int    g_cursor[N_NODES];
__device__ int    g_total;
__device__ float  g_sum[D_HID];
__device__ float  g_sumsq[D_HID];
__device__ float  g_scale[D_HID];
__device__ float  g_shift[D_HID];

// ---------------- weights in constant memory ----------------
__constant__ float4 c_W1l[D_HID * D_IN / 4];
__constant__ float4 c_W1r[D_HID * D_IN / 4];
__constant__ float  c_b1[D_HID];
__constant__ float4 c_W2l[D_OUT * D_HID / 4];
__constant__ float4 c_W2r[D_OUT * D_HID / 4];
__constant__ float  c_b2[D_OUT];

// ---------------- packed fp32x2 helpers (FFMA2: 2 exact fp32 MACs / issue) --
__device__ __forceinline__ void ffma2(unsigned long long& acc,
                                      unsigned long long a,
                                      unsigned long long b) {
    asm("fma.rn.f32x2 %0, %1, %2, %0;" : "+l"(acc) : "l"(a), "l"(b));
}
__device__ __forceinline__ unsigned long long pack2(float lo, float hi) {
    unsigned long long r;
    asm("mov.b64 %0, {%1, %2};" : "=l"(r) : "f"(lo), "f"(hi));
    return r;
}
__device__ __forceinline__ float2 unpack2(unsigned long long v) {
    float2 r;
    asm("mov.b64 {%0, %1}, %2;" : "=f"(r.x), "=f"(r.y) : "l"(v));
    return r;
}

// ---------------- CSR construction ----------------
__global__ void k_zero() {
    int i = blockIdx.x * blockDim.x + threadIdx.x;
    int stride = gridDim.x * blockDim.x;
    for (int t = i; t < N_NODES; t += stride) g_cnt[t] = 0;
    if (i < D_HID) { g_sum[i] = 0.f; g_sumsq[i] = 0.f; }
    if (i == 0) g_total = 0;
}

__global__ void k_count(const int* __restrict__ dst) {
    int t = blockIdx.x * blockDim.x + threadIdx.x;
    int e = t * 4;
    if (e + 4 <= E_EDGES) {
        int4 d4 = *reinterpret_cast<const int4*>(dst + e);
        atomicAdd(&g_cnt[d4.x], 1);
        atomicAdd(&g_cnt[d4.y], 1);
        atomicAdd(&g_cnt[d4.z], 1);
        atomicAdd(&g_cnt[d4.w], 1);
    } else {
        for (int k = e; k < E_EDGES; k++) atomicAdd(&g_cnt[dst[k]], 1);
    }
}

// Warp-aggregated slot allocation.
__global__ void k_alloc() {
    int n = blockIdx.x * blockDim.x + threadIdx.x;
    int lane = threadIdx.x & 31;
    int cnt = (n < N_NODES) ? g_cnt[n] : 0;
    int incl = cnt;
#pragma unroll
    for (int o = 1; o < 32; o <<= 1) {
        int v = __shfl_up_sync(0xffffffffu, incl, o);
        if (lane >= o) incl += v;
    }
    int base = 0;
    if (lane == 31) base = atomicAdd(&g_total, incl);
    base = __shfl_sync(0xffffffffu, base, 31);
    if (n < N_NODES) {
        int rs = base + incl - cnt;
        g_rowstart[n] = rs;
        g_cursor[n] = rs;
    }
}

__global__ void k_fill(const int* __restrict__ src, const int* __restrict__ dst) {
    int t = blockIdx.x * blockDim.x + threadIdx.x;
    int e = t * 4;
    if (e + 4 <= E_EDGES) {
        int4 d4 = *reinterpret_cast<const int4*>(dst + e);
        int4 s4 = *reinterpret_cast<const int4*>(src + e);
        int p0 = atomicAdd(&g_cursor[d4.x], 1);
        int p1 = atomicAdd(&g_cursor[d4.y], 1);
        int p2 = atomicAdd(&g_cursor[d4.z], 1);
        int p3 = atomicAdd(&g_cursor[d4.w], 1);
        g_adj[p0] = s4.x;
        g_adj[p1] = s4.y;
        g_adj[p2] = s4.z;
        g_adj[p3] = s4.w;
    } else {
        for (int k = e; k < E_EDGES; k++) {
            int pos = atomicAdd(&g_cursor[dst[k]], 1);
            g_adj[pos] = src[k];
        }
    }
}

// ---------------- aggregation 1: mean of neighbor x (64-dim) ----------------
// warp = 2 nodes, 16 lanes each hold one float4 of the row; neighbor loop x4.
__global__ __launch_bounds__(256) void k_agg1(const float4* __restrict__ x) {
    int gw = (blockIdx.x * blockDim.x + threadIdx.x) >> 5;
    int lane = threadIdx.x & 31;
    int sub = lane >> 4;
    int q = lane & 15;
    int n = gw * 2 + sub;
    if (n >= N_NODES) return;
    int beg = g_rowstart[n];
    int cnt = g_cnt[n];
    float4 acc = make_float4(0.f, 0.f, 0.f, 0.f);
    int i = 0;
    for (; i + 4 <= cnt; i += 4) {
        int s0 = g_adj[beg + i];
        int s1 = g_adj[beg + i + 1];
        int s2 = g_adj[beg + i + 2];
        int s3 = g_adj[beg + i + 3];
        float4 v0 = x[(size_t)s0 * 16 + q];
        float4 v1 = x[(size_t)s1 * 16 + q];
        float4 v2 = x[(size_t)s2 * 16 + q];
        float4 v3 = x[(size_t)s3 * 16 + q];
        acc.x += (v0.x + v1.x) + (v2.x + v3.x);
        acc.y += (v0.y + v1.y) + (v2.y + v3.y);
        acc.z += (v0.z + v1.z) + (v2.z + v3.z);
        acc.w += (v0.w + v1.w) + (v2.w + v3.w);
    }
    for (; i < cnt; i++) {
        int s = g_adj[beg + i];
        float4 v = x[(size_t)s * 16 + q];
        acc.x += v.x; acc.y += v.y; acc.z += v.z; acc.w += v.w;
    }
    float inv = 1.0f / (float)(cnt > 0 ? cnt : 1);
    acc.x *= inv; acc.y *= inv; acc.z *= inv; acc.w *= inv;
    g_agg1[(size_t)n * 16 + q] = acc;
}

// ---------------- layer 1 GEMM (FFMA2) ----------------
// h_pre[n][j] = b1[j] + W1l[j]·agg1[n] + W1r[j]·x[n]
__global__ __launch_bounds__(128) void k_gemm1(const float4* __restrict__ x) {
    int n = blockIdx.x * 128 + threadIdx.x;
    if (n >= N_NODES) return;
    ulonglong2 xv[16], av[16];
    const ulonglong2* xp = reinterpret_cast<const ulonglong2*>(x + (size_t)n * 16);
    const ulonglong2* ap = reinterpret_cast<const ulonglong2*>(g_agg1 + (size_t)n * 16);
#pragma unroll
    for (int c = 0; c < 16; c++) { xv[c] = xp[c]; av[c] = ap[c]; }
    const ulonglong2* wl64 = reinterpret_cast<const ulonglong2*>(c_W1l);
    const ulonglong2* wr64 = reinterpret_cast<const ulonglong2*>(c_W1r);
    float* hp = reinterpret_cast<float*>(g_h) + (size_t)n * D_HID;
#pragma unroll 1
    for (int j = 0; j < D_HID; j++) {
        unsigned long long a0 = pack2(c_b1[j], 0.f);
        unsigned long long a1 = 0ull, a2 = 0ull, a3 = 0ull;
#pragma unroll
        for (int c = 0; c < 16; c++) {
            ulonglong2 wl = wl64[j * 16 + c];
            ulonglong2 wr = wr64[j * 16 + c];
            ffma2(a0, wl.x, av[c].x);
            ffma2(a1, wl.y, av[c].y);
            ffma2(a2, wr.x, xv[c].x);
            ffma2(a3, wr.y, xv[c].y);
        }
        float2 f0 = unpack2(a0), f1 = unpack2(a1), f2 = unpack2(a2), f3 = unpack2(a3);
        hp[j] = ((f0.x + f0.y) + (f1.x + f1.y)) + ((f2.x + f2.y) + (f3.x + f3.y));
    }
}

// ---------------- BN stats ----------------
#define STATS_ROWS 256
__global__ void k_colstats() {
    __shared__ float ssum[256];
    __shared__ float ssq[256];
    const float* h = reinterpret_cast<const float*>(g_h);
    int j = threadIdx.x & 63;
    int rs = threadIdx.x >> 6;
    int row0 = blockIdx.x * STATS_ROWS;
    float s = 0.f, q = 0.f;
    int rend = row0 + STATS_ROWS;
    if (rend > N_NODES) rend = N_NODES;
    for (int r = row0 + rs; r < rend; r += 4) {
        float v = h[(size_t)r * D_HID + j];
        s += v;
        q += v * v;
    }
    ssum[threadIdx.x] = s;
    ssq[threadIdx.x] = q;
    __syncthreads();
    if (rs == 0) {
        atomicAdd(&g_sum[j], ssum[j] + ssum[64 + j] + ssum[128 + j] + ssum[192 + j]);
        atomicAdd(&g_sumsq[j], ssq[j] + ssq[64 + j] + ssq[128 + j] + ssq[192 + j]);
    }
}

__global__ void k_bnfin(const float* __restrict__ gamma, const float* __restrict__ beta) {
    int j = threadIdx.x;
    if (j < D_HID) {
        float mu = g_sum[j] * (1.0f / (float)N_NODES);
        float var = g_sumsq[j] * (1.0f / (float)N_NODES) - mu * mu;
        float rs = rsqrtf(var + BN_EPS);
        float sc = gamma[j] * rs;
        g_scale[j] = sc;
        g_shift[j] = beta[j] - mu * sc;
    }
}

// ------- BN + ReLU + both layer-2 projections (FFMA2), no h writeback -------
// p[n]   = relu(bn(h[n])) @ W2l.T          -> g_p  (aggregated next)
// out[n] = b2 + relu(bn(h[n])) @ W2r.T     -> out  (agg2 adds neighbor mean)
__global__ __launch_bounds__(128) void k_bnrelu_proj(float4* __restrict__ out) {
    int n = blockIdx.x * 128 + threadIdx.x;
    if (n >= N_NODES) return;
    float4 hv[16];
    const float4* hp = g_h + (size_t)n * 16;
#pragma unroll
    for (int c = 0; c < 16; c++) {
        float4 sc = reinterpret_cast<const float4*>(g_scale)[c];
        float4 sh = reinterpret_cast<const float4*>(g_shift)[c];
        float4 h = hp[c];
        h.x = fmaxf(fmaf(h.x, sc.x, sh.x), 0.f);
        h.y = fmaxf(fmaf(h.y, sc.y, sh.y), 0.f);
        h.z = fmaxf(fmaf(h.z, sc.z, sh.z), 0.f);
        h.w = fmaxf(fmaf(h.w, sc.w, sh.w), 0.f);
        hv[c] = h;
    }
    const ulonglong2* hv64 = reinterpret_cast<const ulonglong2*>(hv);
    const ulonglong2* wl64 = reinterpret_cast<const ulonglong2*>(c_W2l);
    const ulonglong2* wr64 = reinterpret_cast<const ulonglong2*>(c_W2r);
    float4* pp = g_p + (size_t)n * 10;
    float4* op = out + (size_t)n * 10;
    float pj[4], oj[4];
#pragma unroll 1
    for (int jb = 0; jb < 10; jb++) {
#pragma unroll
        for (int u = 0; u < 4; u++) {
            int j = jb * 4 + u;
            unsigned long long a0 = 0ull, a1 = 0ull;
            unsigned long long b0 = pack2(c_b2[j], 0.f), b1 = 0ull;
#pragma unroll
            for (int c = 0; c < 16; c++) {
                ulonglong2 wl = wl64[j * 16 + c];
                ulonglong2 wr = wr64[j * 16 + c];
                ffma2(a0, wl.x, hv64[c].x);
                ffma2(a1, wl.y, hv64[c].y);
                ffma2(b0, wr.x, hv64[c].x);
                ffma2(b1, wr.y, hv64[c].y);
            }
            float2 f0 = unpack2(a0), f1 = unpack2(a1);
            float2 g0 = unpack2(b0), g1 = unpack2(b1);
            pj[u] = (f0.x + f0.y) + (f1.x + f1.y);
            oj[u] = (g0.x + g0.y) + (g1.x + g1.y);
        }
        pp[jb] = make_float4(pj[0], pj[1], pj[2], pj[3]);
        op[jb] = make_float4(oj[0], oj[1], oj[2], oj[3]);
    }
}

// ------- aggregation 2: out[n] += mean of neighbor p (40-dim) -------
// warp = 3 nodes, 10 lanes each; neighbor loop x4.
__global__ __launch_bounds__(256) void k_agg2(float4* __restrict__ out) {
    int gw = (blockIdx.x * blockDim.x + threadIdx.x) >> 5;
    int lane = threadIdx.x & 31;
    int sub = lane / 10;
    int q = lane - sub * 10;
    int n = gw * 3 + sub;
    if (sub >= 3 || n >= N_NODES) return;
    int beg = g_rowstart[n];
    int cnt = g_cnt[n];
    float4 acc = make_float4(0.f, 0.f, 0.f, 0.f);
    int i = 0;
    for (; i + 4 <= cnt; i += 4) {
        int s0 = g_adj[beg + i];
        int s1 = g_adj[beg + i + 1];
        int s2 = g_adj[beg + i + 2];
        int s3 = g_adj[beg + i + 3];
        float4 v0 = g_p[(size_t)s0 * 10 + q];
        float4 v1 = g_p[(size_t)s1 * 10 + q];
        float4 v2 = g_p[(size_t)s2 * 10 + q];
        float4 v3 = g_p[(size_t)s3 * 10 + q];
        acc.x += (v0.x + v1.x) + (v2.x + v3.x);
        acc.y += (v0.y + v1.y) + (v2.y + v3.y);
        acc.z += (v0.z + v1.z) + (v2.z + v3.z);
        acc.w += (v0.w + v1.w) + (v2.w + v3.w);
    }
    for (; i < cnt; i++) {
        int s = g_adj[beg + i];
        float4 v = g_p[(size_t)s * 10 + q];
        acc.x += v.x; acc.y += v.y; acc.z += v.z; acc.w += v.w;
    }
    float inv = 1.0f / (float)(cnt > 0 ? cnt : 1);
    float4 o = out[(size_t)n * 10 + q];
    o.x += acc.x * inv; o.y += acc.y * inv; o.z += acc.z * inv; o.w += acc.w * inv;
    out[(size_t)n * 10 + q] = o;
}

// ---------------- launch ----------------
extern "C" void kernel_launch(void* const* d_in, const int* in_sizes, int n_in,
                              void* d_out, int out_size) {
    const float4* x     = (const float4*)d_in[0];
    const int*    ei    = (const int*)d_in[1];   // int32 (jax x64 disabled)
    const float*  gamma = (const float*)d_in[5];
    const float*  beta  = (const float*)d_in[6];
    const int* src = ei;
    const int* dst = ei + E_EDGES;

    cudaMemcpyToSymbolAsync(c_W1l, d_in[2], D_HID * D_IN * sizeof(float), 0, cudaMemcpyDeviceToDevice, 0);
    cudaMemcpyToSymbolAsync(c_W1r, d_in[3], D_HID * D_IN * sizeof(float), 0, cudaMemcpyDeviceToDevice, 0);
    cudaMemcpyToSymbolAsync(c_b1,  d_in[4], D_HID * sizeof(float),        0, cudaMemcpyDeviceToDevice, 0);
    cudaMemcpyToSymbolAsync(c_W2l, d_in[7], D_OUT * D_HID * sizeof(float), 0, cudaMemcpyDeviceToDevice, 0);
    cudaMemcpyToSymbolAsync(c_W2r, d_in[8], D_OUT * D_HID * sizeof(float), 0, cudaMemcpyDeviceToDevice, 0);
    cudaMemcpyToSymbolAsync(c_b2,  d_in[9], D_OUT * sizeof(float),         0, cudaMemcpyDeviceToDevice, 0);

    // CSR build (shared by both layers)
    k_zero<<<256, 256>>>();
    k_count<<<(E_EDGES / 4 + 255) / 256, 256>>>(dst);
    k_alloc<<<(N_NODES + 127) / 128, 128>>>();
    k_fill<<<(E_EDGES / 4 + 255) / 256, 256>>>(src, dst);

    // Layer 1
    k_agg1<<<(N_NODES / 2 + 7) / 8, 256>>>(x);
    k_gemm1<<<(N_NODES + 127) / 128, 128>>>(x);

    // BatchNorm + ReLU + both layer-2 projections
    k_colstats<<<(N_NODES + STATS_ROWS - 1) / STATS_ROWS, 256>>>();
    k_bnfin<<<1, 64>>>(gamma, beta);
    k_bnrelu_proj<<<(N_NODES + 127) / 128, 128>>>((float4*)d_out);

    // Layer 2: add neighbor-mean of p into out
    k_agg2<<<(N_NODES / 3 + 8) / 8, 256>>>((float4*)d_out);
}

// round 6
// speedup vs baseline: 1.4146x; 1.0540x over previous
#include <cuda_runtime.h>
#include <cstdint>

#define N_NODES 100000
#define E_EDGES 1600000
#define D_IN   64
#define D_HID  64
#define D_OUT  40
#define BN_EPS 1e-5f
#define ELL_W  64   // max degree capacity; P(deg>63) ~ 1e-20 for Poisson(16)

// ---------------- scratch (float4 => 16B aligned) ----------------
__device__ float4 g_agg1[(size_t)N_NODES * 16];   // mean of neighbor x
__device__ float4 g_h[(size_t)N_NODES * 16];      // layer-1 pre-BN output
__device__ float4 g_p[(size_t)N_NODES * 10];      // relu(bn(h)) @ W2l.T
__device__ int    g_adj[(size_t)N_NODES * ELL_W]; // ELL adjacency, 16B-aligned rows
__device__ int    g_cnt[N_NODES];
__device__ float  g_sum[D_HID];
__device__ float  g_sumsq[D_HID];

// ---------------- weights in constant memory (uniform -> LDCU path) -------
__constant__ float4 c_W1l[D_HID * D_IN / 4];
__constant__ float4 c_W1r[D_HID * D_IN / 4];
__constant__ float  c_b1[D_HID];
__constant__ float4 c_W2l[D_OUT * D_HID / 4];
__constant__ float4 c_W2r[D_OUT * D_HID / 4];
__constant__ float  c_b2[D_OUT];

// ---------------- packed fp32x2 helpers (FFMA2) ----------------
__device__ __forceinline__ void ffma2(unsigned long long& acc,
                                      unsigned long long a,
                                      unsigned long long b) {
    asm("fma.rn.f32x2 %0, %1, %2, %0;" : "+l"(acc) : "l"(a), "l"(b));
}
__device__ __forceinline__ unsigned long long pack2(float lo, float hi) {
    unsigned long long r;
    asm("mov.b64 %0, {%1, %2};" : "=l"(r) : "f"(lo), "f"(hi));
    return r;
}
__device__ __forceinline__ float2 unpack2(unsigned long long v) {
    float2 r;
    asm("mov.b64 {%0, %1}, %2;" : "=f"(r.x), "=f"(r.y) : "l"(v));
    return r;
}

// ---------------- init ----------------
__global__ void k_zero() {
    int i = blockIdx.x * blockDim.x + threadIdx.x;
    int stride = gridDim.x * blockDim.x;
    for (int t = i; t < N_NODES; t += stride) g_cnt[t] = 0;
    if (i < D_HID) { g_sum[i] = 0.f; g_sumsq[i] = 0.f; }
}

// ---------------- single-pass ELL build (count + fill fused) ----------------
// 8 edges per thread: two int4 loads each for src/dst, 8 independent atomics.
__global__ void k_countfill(const int* __restrict__ src, const int* __restrict__ dst) {
    int t = blockIdx.x * blockDim.x + threadIdx.x;
    int e = t * 8;
    if (e + 8 <= E_EDGES) {
        int4 da = *reinterpret_cast<const int4*>(dst + e);
        int4 db = *reinterpret_cast<const int4*>(dst + e + 4);
        int4 sa = *reinterpret_cast<const int4*>(src + e);
        int4 sb = *reinterpret_cast<const int4*>(src + e + 4);
        int p0 = atomicAdd(&g_cnt[da.x], 1);
        int p1 = atomicAdd(&g_cnt[da.y], 1);
        int p2 = atomicAdd(&g_cnt[da.z], 1);
        int p3 = atomicAdd(&g_cnt[da.w], 1);
        int p4 = atomicAdd(&g_cnt[db.x], 1);
        int p5 = atomicAdd(&g_cnt[db.y], 1);
        int p6 = atomicAdd(&g_cnt[db.z], 1);
        int p7 = atomicAdd(&g_cnt[db.w], 1);
        if (p0 < ELL_W) g_adj[(size_t)da.x * ELL_W + p0] = sa.x;
        if (p1 < ELL_W) g_adj[(size_t)da.y * ELL_W + p1] = sa.y;
        if (p2 < ELL_W) g_adj[(size_t)da.z * ELL_W + p2] = sa.z;
        if (p3 < ELL_W) g_adj[(size_t)da.w * ELL_W + p3] = sa.w;
        if (p4 < ELL_W) g_adj[(size_t)db.x * ELL_W + p4] = sb.x;
        if (p5 < ELL_W) g_adj[(size_t)db.y * ELL_W + p5] = sb.y;
        if (p6 < ELL_W) g_adj[(size_t)db.z * ELL_W + p6] = sb.z;
        if (p7 < ELL_W) g_adj[(size_t)db.w * ELL_W + p7] = sb.w;
    } else {
        for (int k = e; k < E_EDGES; k++) {
            int d = dst[k];
            int pos = atomicAdd(&g_cnt[d], 1);
            if (pos < ELL_W) g_adj[(size_t)d * ELL_W + pos] = src[k];
        }
    }
}

// ---------------- aggregation 1: mean of neighbor x (64-dim) ----------------
// warp = 2 nodes, 16 lanes each hold one float4; int4 adjacency loads.
__global__ __launch_bounds__(256) void k_agg1(const float4* __restrict__ x) {
    int gw = (blockIdx.x * blockDim.x + threadIdx.x) >> 5;
    int lane = threadIdx.x & 31;
    int sub = lane >> 4;
    int q = lane & 15;
    int n = gw * 2 + sub;
    if (n >= N_NODES) return;
    const int* row = g_adj + (size_t)n * ELL_W;
    int cnt = g_cnt[n];
    if (cnt > ELL_W) cnt = ELL_W;
    float4 acc = make_float4(0.f, 0.f, 0.f, 0.f);
    int i = 0;
    for (; i + 4 <= cnt; i += 4) {
        int4 s4 = *reinterpret_cast<const int4*>(row + i);
        float4 v0 = x[(size_t)s4.x * 16 + q];
        float4 v1 = x[(size_t)s4.y * 16 + q];
        float4 v2 = x[(size_t)s4.z * 16 + q];
        float4 v3 = x[(size_t)s4.w * 16 + q];
        acc.x += (v0.x + v1.x) + (v2.x + v3.x);
        acc.y += (v0.y + v1.y) + (v2.y + v3.y);
        acc.z += (v0.z + v1.z) + (v2.z + v3.z);
        acc.w += (v0.w + v1.w) + (v2.w + v3.w);
    }
    for (; i < cnt; i++) {
        int s = row[i];
        float4 v = x[(size_t)s * 16 + q];
        acc.x += v.x; acc.y += v.y; acc.z += v.z; acc.w += v.w;
    }
    float inv = 1.0f / (float)(cnt > 0 ? cnt : 1);
    acc.x *= inv; acc.y *= inv; acc.z *= inv; acc.w *= inv;
    g_agg1[(size_t)n * 16 + q] = acc;
}

// ---------------- layer 1 GEMM (FFMA2, constant weights) ----------------
__global__ __launch_bounds__(128) void k_gemm1(const float4* __restrict__ x) {
    int n = blockIdx.x * 128 + threadIdx.x;
    if (n >= N_NODES) return;
    ulonglong2 xv[16], av[16];
    const ulonglong2* xp = reinterpret_cast<const ulonglong2*>(x + (size_t)n * 16);
    const ulonglong2* ap = reinterpret_cast<const ulonglong2*>(g_agg1 + (size_t)n * 16);
#pragma unroll
    for (int c = 0; c < 16; c++) { xv[c] = xp[c]; av[c] = ap[c]; }
    const ulonglong2* wl64 = reinterpret_cast<const ulonglong2*>(c_W1l);
    const ulonglong2* wr64 = reinterpret_cast<const ulonglong2*>(c_W1r);
    float* hp = reinterpret_cast<float*>(g_h) + (size_t)n * D_HID;
#pragma unroll 1
    for (int j = 0; j < D_HID; j++) {
        unsigned long long a0 = pack2(c_b1[j], 0.f);
        unsigned long long a1 = 0ull, a2 = 0ull, a3 = 0ull;
#pragma unroll
        for (int c = 0; c < 16; c++) {
            ulonglong2 wl = wl64[j * 16 + c];
            ulonglong2 wr = wr64[j * 16 + c];
            ffma2(a0, wl.x, av[c].x);
            ffma2(a1, wl.y, av[c].y);
            ffma2(a2, wr.x, xv[c].x);
            ffma2(a3, wr.y, xv[c].y);
        }
        float2 f0 = unpack2(a0), f1 = unpack2(a1), f2 = unpack2(a2), f3 = unpack2(a3);
        hp[j] = ((f0.x + f0.y) + (f1.x + f1.y)) + ((f2.x + f2.y) + (f3.x + f3.y));
    }
}

// ---------------- BN stats: vectorized float4 column sums ----------------
#define SROWS 512
__global__ __launch_bounds__(256) void k_colstats() {
    __shared__ float4 ssum[256];
    __shared__ float4 ssq[256];
    int j4 = threadIdx.x & 15;        // float4 column group 0..15
    int rs = threadIdx.x >> 4;        // 0..15
    int row0 = blockIdx.x * SROWS;
    int rend = row0 + SROWS;
    if (rend > N_NODES) rend = N_NODES;
    float4 s = make_float4(0.f, 0.f, 0.f, 0.f);
    float4 q = make_float4(0.f, 0.f, 0.f, 0.f);
    for (int r = row0 + rs; r < rend; r += 16) {
        float4 v = g_h[(size_t)r * 16 + j4];
        s.x += v.x; s.y += v.y; s.z += v.z; s.w += v.w;
        q.x += v.x * v.x; q.y += v.y * v.y; q.z += v.z * v.z; q.w += v.w * v.w;
    }
    ssum[threadIdx.x] = s;
    ssq[threadIdx.x] = q;
    __syncthreads();
    for (int stride = 128; stride >= 16; stride >>= 1) {
        if (threadIdx.x < stride) {
            float4 a = ssum[threadIdx.x + stride];
            float4 b = ssq[threadIdx.x + stride];
            float4 sa = ssum[threadIdx.x];
            float4 sb = ssq[threadIdx.x];
            sa.x += a.x; sa.y += a.y; sa.z += a.z; sa.w += a.w;
            sb.x += b.x; sb.y += b.y; sb.z += b.z; sb.w += b.w;
            ssum[threadIdx.x] = sa;
            ssq[threadIdx.x] = sb;
        }
        __syncthreads();
    }
    if (threadIdx.x < 16) {
        float4 sa = ssum[threadIdx.x];
        float4 sb = ssq[threadIdx.x];
        int jb = threadIdx.x * 4;
        atomicAdd(&g_sum[jb + 0], sa.x);
        atomicAdd(&g_sum[jb + 1], sa.y);
        atomicAdd(&g_sum[jb + 2], sa.z);
        atomicAdd(&g_sum[jb + 3], sa.w);
        atomicAdd(&g_sumsq[jb + 0], sb.x);
        atomicAdd(&g_sumsq[jb + 1], sb.y);
        atomicAdd(&g_sumsq[jb + 2], sb.z);
        atomicAdd(&g_sumsq[jb + 3], sb.w);
    }
}

// ------- BN finalize (in-block) + ReLU + both layer-2 projections -------
__global__ __launch_bounds__(128) void k_bnrelu_proj(float4* __restrict__ out,
                                                     const float* __restrict__ gamma,
                                                     const float* __restrict__ beta) {
    __shared__ float4 s_scale[16];
    __shared__ float4 s_shift[16];
    if (threadIdx.x < D_HID) {
        int j = threadIdx.x;
        float mu = g_sum[j] * (1.0f / (float)N_NODES);
        float var = g_sumsq[j] * (1.0f / (float)N_NODES) - mu * mu;
        float rs = rsqrtf(var + BN_EPS);
        float sc = gamma[j] * rs;
        reinterpret_cast<float*>(s_scale)[j] = sc;
        reinterpret_cast<float*>(s_shift)[j] = beta[j] - mu * sc;
    }
    __syncthreads();
    int n = blockIdx.x * 128 + threadIdx.x;
    if (n >= N_NODES) return;
    float4 hv[16];
    const float4* hp = g_h + (size_t)n * 16;
#pragma unroll
    for (int c = 0; c < 16; c++) {
        float4 sc = s_scale[c];
        float4 sh = s_shift[c];
        float4 h = hp[c];
        h.x = fmaxf(fmaf(h.x, sc.x, sh.x), 0.f);
        h.y = fmaxf(fmaf(h.y, sc.y, sh.y), 0.f);
        h.z = fmaxf(fmaf(h.z, sc.z, sh.z), 0.f);
        h.w = fmaxf(fmaf(h.w, sc.w, sh.w), 0.f);
        hv[c] = h;
    }
    const ulonglong2* hv64 = reinterpret_cast<const ulonglong2*>(hv);
    const ulonglong2* wl64 = reinterpret_cast<const ulonglong2*>(c_W2l);
    const ulonglong2* wr64 = reinterpret_cast<const ulonglong2*>(c_W2r);
    float4* pp = g_p + (size_t)n * 10;
    float4* op = out + (size_t)n * 10;
    float pj[4], oj[4];
#pragma unroll 1
    for (int jb = 0; jb < 10; jb++) {
#pragma unroll
        for (int u = 0; u < 4; u++) {
            int j = jb * 4 + u;
            unsigned long long a0 = 0ull, a1 = 0ull;
            unsigned long long b0 = pack2(c_b2[j], 0.f), b1 = 0ull;
#pragma unroll
            for (int c = 0; c < 16; c++) {
                ulonglong2 wl = wl64[j * 16 + c];
                ulonglong2 wr = wr64[j * 16 + c];
                ffma2(a0, wl.x, hv64[c].x);
                ffma2(a1, wl.y, hv64[c].y);
                ffma2(b0, wr.x, hv64[c].x);
                ffma2(b1, wr.y, hv64[c].y);
            }
            float2 f0 = unpack2(a0), f1 = unpack2(a1);
            float2 g0 = unpack2(b0), g1 = unpack2(b1);
            pj[u] = (f0.x + f0.y) + (f1.x + f1.y);
            oj[u] = (g0.x + g0.y) + (g1.x + g1.y);
        }
        pp[jb] = make_float4(pj[0], pj[1], pj[2], pj[3]);
        op[jb] = make_float4(oj[0], oj[1], oj[2], oj[3]);
    }
}

// ------- aggregation 2: out[n] += mean of neighbor p (40-dim) -------
__global__ __launch_bounds__(256) void k_agg2(float4* __restrict__ out) {
    int gw = (blockIdx.x * blockDim.x + threadIdx.x) >> 5;
    int lane = threadIdx.x & 31;
    int sub = lane / 10;
    int q = lane - sub * 10;
    int n = gw * 3 + sub;
    if (sub >= 3 || n >= N_NODES) return;
    const int* row = g_adj + (size_t)n * ELL_W;
    int cnt = g_cnt[n];
    if (cnt > ELL_W) cnt = ELL_W;
    float4 acc = make_float4(0.f, 0.f, 0.f, 0.f);
    int i = 0;
    for (; i + 4 <= cnt; i += 4) {
        int4 s4 = *reinterpret_cast<const int4*>(row + i);
        float4 v0 = g_p[(size_t)s4.x * 10 + q];
        float4 v1 = g_p[(size_t)s4.y * 10 + q];
        float4 v2 = g_p[(size_t)s4.z * 10 + q];
        float4 v3 = g_p[(size_t)s4.w * 10 + q];
        acc.x += (v0.x + v1.x) + (v2.x + v3.x);
        acc.y += (v0.y + v1.y) + (v2.y + v3.y);
        acc.z += (v0.z + v1.z) + (v2.z + v3.z);
        acc.w += (v0.w + v1.w) + (v2.w + v3.w);
    }
    for (; i < cnt; i++) {
        int s = row[i];
        float4 v = g_p[(size_t)s * 10 + q];
        acc.x += v.x; acc.y += v.y; acc.z += v.z; acc.w += v.w;
    }
    float inv = 1.0f / (float)(cnt > 0 ? cnt : 1);
    float4 o = out[(size_t)n * 10 + q];
    o.x += acc.x * inv; o.y += acc.y * inv; o.z += acc.z * inv; o.w += acc.w * inv;
    out[(size_t)n * 10 + q] = o;
}

// ---------------- launch ----------------
extern "C" void kernel_launch(void* const* d_in, const int* in_sizes, int n_in,
                              void* d_out, int out_size) {
    const float4* x     = (const float4*)d_in[0];
    const int*    ei    = (const int*)d_in[1];   // int32 (jax x64 disabled)
    const float*  gamma = (const float*)d_in[5];
    const float*  beta  = (const float*)d_in[6];
    const int* src = ei;
    const int* dst = ei + E_EDGES;

    cudaMemcpyToSymbolAsync(c_W1l, d_in[2], D_HID * D_IN * sizeof(float), 0, cudaMemcpyDeviceToDevice, 0);
    cudaMemcpyToSymbolAsync(c_W1r, d_in[3], D_HID * D_IN * sizeof(float), 0, cudaMemcpyDeviceToDevice, 0);
    cudaMemcpyToSymbolAsync(c_b1,  d_in[4], D_HID * sizeof(float),        0, cudaMemcpyDeviceToDevice, 0);
    cudaMemcpyToSymbolAsync(c_W2l, d_in[7], D_OUT * D_HID * sizeof(float), 0, cudaMemcpyDeviceToDevice, 0);
    cudaMemcpyToSymbolAsync(c_W2r, d_in[8], D_OUT * D_HID * sizeof(float), 0, cudaMemcpyDeviceToDevice, 0);
    cudaMemcpyToSymbolAsync(c_b2,  d_in[9], D_OUT * sizeof(float),         0, cudaMemcpyDeviceToDevice, 0);

    // ELL adjacency build (count + fill fused, shared by both layers)
    k_zero<<<256, 256>>>();
    k_countfill<<<(E_EDGES / 8 + 255) / 256, 256>>>(src, dst);

    // Layer 1
    k_agg1<<<(N_NODES / 2 + 7) / 8, 256>>>(x);
    k_gemm1<<<(N_NODES + 127) / 128, 128>>>(x);

    // BN stats + (finalize+ReLU+projections)
    k_colstats<<<(N_NODES + SROWS - 1) / SROWS, 256>>>();
    k_bnrelu_proj<<<(N_NODES + 127) / 128, 128>>>((float4*)d_out, gamma, beta);

    // Layer 2: add neighbor-mean of p into out
    k_agg2<<<(N_NODES / 3 + 8) / 8, 256>>>((float4*)d_out);
}

// round 7
// speedup vs baseline: 1.4802x; 1.0464x over previous
#include <cuda_runtime.h>
#include <cstdint>

#define N_NODES 100000
#define E_EDGES 1600000
#define D_IN   64
#define D_HID  64
#define D_OUT  40
#define BN_EPS 1e-5f
#define ELL_W  64   // max degree capacity; P(deg>63) ~ 1e-20 for Poisson(16)

// ---------------- scratch (float4 => 16B aligned) ----------------
__device__ float4 g_agg1[(size_t)N_NODES * 16];   // mean of neighbor x
__device__ float4 g_h[(size_t)N_NODES * 16];      // layer-1 pre-BN output
__device__ float4 g_p[(size_t)N_NODES * 10];      // relu(bn(h)) @ W2l.T
__device__ int    g_adj[(size_t)N_NODES * ELL_W]; // ELL adjacency, 16B-aligned rows
__device__ int    g_cnt[N_NODES];
__device__ float  g_sum[D_HID];
__device__ float  g_sumsq[D_HID];

// Weights in __device__ globals (coalesced LDG -> smem staging per block)
__device__ float4 g_W1[2048];   // [0:1024) = W1l rows, [1024:2048) = W1r rows
__device__ float4 g_W2[1280];   // [0:640)  = W2l rows, [640:1280)  = W2r rows
__constant__ float c_b1[D_HID];
__constant__ float c_b2[D_OUT];

// ---------------- packed fp32x2 helpers (FFMA2) ----------------
__device__ __forceinline__ void ffma2(unsigned long long& acc,
                                      unsigned long long a,
                                      unsigned long long b) {
    asm("fma.rn.f32x2 %0, %1, %2, %0;" : "+l"(acc) : "l"(a), "l"(b));
}
__device__ __forceinline__ unsigned long long pack2(float lo, float hi) {
    unsigned long long r;
    asm("mov.b64 %0, {%1, %2};" : "=l"(r) : "f"(lo), "f"(hi));
    return r;
}
__device__ __forceinline__ float2 unpack2(unsigned long long v) {
    float2 r;
    asm("mov.b64 {%0, %1}, %2;" : "=f"(r.x), "=f"(r.y) : "l"(v));
    return r;
}

// ---------------- init ----------------
__global__ void k_zero() {
    int i = blockIdx.x * blockDim.x + threadIdx.x;
    int stride = gridDim.x * blockDim.x;
    for (int t = i; t < N_NODES; t += stride) g_cnt[t] = 0;
    if (i < D_HID) { g_sum[i] = 0.f; g_sumsq[i] = 0.f; }
}

// ---------------- single-pass ELL build (count + fill fused) ----------------
__global__ void k_countfill(const int* __restrict__ src, const int* __restrict__ dst) {
    int t = blockIdx.x * blockDim.x + threadIdx.x;
    int e = t * 8;
    if (e + 8 <= E_EDGES) {
        int4 da = *reinterpret_cast<const int4*>(dst + e);
        int4 db = *reinterpret_cast<const int4*>(dst + e + 4);
        int4 sa = *reinterpret_cast<const int4*>(src + e);
        int4 sb = *reinterpret_cast<const int4*>(src + e + 4);
        int p0 = atomicAdd(&g_cnt[da.x], 1);
        int p1 = atomicAdd(&g_cnt[da.y], 1);
        int p2 = atomicAdd(&g_cnt[da.z], 1);
        int p3 = atomicAdd(&g_cnt[da.w], 1);
        int p4 = atomicAdd(&g_cnt[db.x], 1);
        int p5 = atomicAdd(&g_cnt[db.y], 1);
        int p6 = atomicAdd(&g_cnt[db.z], 1);
        int p7 = atomicAdd(&g_cnt[db.w], 1);
        if (p0 < ELL_W) g_adj[(size_t)da.x * ELL_W + p0] = sa.x;
        if (p1 < ELL_W) g_adj[(size_t)da.y * ELL_W + p1] = sa.y;
        if (p2 < ELL_W) g_adj[(size_t)da.z * ELL_W + p2] = sa.z;
        if (p3 < ELL_W) g_adj[(size_t)da.w * ELL_W + p3] = sa.w;
        if (p4 < ELL_W) g_adj[(size_t)db.x * ELL_W + p4] = sb.x;
        if (p5 < ELL_W) g_adj[(size_t)db.y * ELL_W + p5] = sb.y;
        if (p6 < ELL_W) g_adj[(size_t)db.z * ELL_W + p6] = sb.z;
        if (p7 < ELL_W) g_adj[(size_t)db.w * ELL_W + p7] = sb.w;
    } else {
        for (int k = e; k < E_EDGES; k++) {
            int d = dst[k];
            int pos = atomicAdd(&g_cnt[d], 1);
            if (pos < ELL_W) g_adj[(size_t)d * ELL_W + pos] = src[k];
        }
    }
}

// ---------------- aggregation 1: mean of neighbor x (64-dim) ----------------
__global__ __launch_bounds__(256) void k_agg1(const float4* __restrict__ x) {
    int gw = (blockIdx.x * blockDim.x + threadIdx.x) >> 5;
    int lane = threadIdx.x & 31;
    int sub = lane >> 4;
    int q = lane & 15;
    int n = gw * 2 + sub;
    if (n >= N_NODES) return;
    const int* row = g_adj + (size_t)n * ELL_W;
    int cnt = g_cnt[n];
    if (cnt > ELL_W) cnt = ELL_W;
    float4 acc = make_float4(0.f, 0.f, 0.f, 0.f);
    int i = 0;
    for (; i + 4 <= cnt; i += 4) {
        int4 s4 = *reinterpret_cast<const int4*>(row + i);
        float4 v0 = x[(size_t)s4.x * 16 + q];
        float4 v1 = x[(size_t)s4.y * 16 + q];
        float4 v2 = x[(size_t)s4.z * 16 + q];
        float4 v3 = x[(size_t)s4.w * 16 + q];
        acc.x += (v0.x + v1.x) + (v2.x + v3.x);
        acc.y += (v0.y + v1.y) + (v2.y + v3.y);
        acc.z += (v0.z + v1.z) + (v2.z + v3.z);
        acc.w += (v0.w + v1.w) + (v2.w + v3.w);
    }
    for (; i < cnt; i++) {
        int s = row[i];
        float4 v = x[(size_t)s * 16 + q];
        acc.x += v.x; acc.y += v.y; acc.z += v.z; acc.w += v.w;
    }
    float inv = 1.0f / (float)(cnt > 0 ? cnt : 1);
    acc.x *= inv; acc.y *= inv; acc.z *= inv; acc.w *= inv;
    g_agg1[(size_t)n * 16 + q] = acc;
}

// ---------------- layer 1 GEMM (FFMA2, smem-staged weights) ----------------
__global__ __launch_bounds__(256) void k_gemm1(const float4* __restrict__ x) {
    __shared__ float4 s_W[2048];   // 32KB: W1l rows then W1r rows
#pragma unroll
    for (int t = 0; t < 8; t++) s_W[threadIdx.x + t * 256] = g_W1[threadIdx.x + t * 256];
    __syncthreads();
    int n = blockIdx.x * 256 + threadIdx.x;
    if (n >= N_NODES) return;
    ulonglong2 xv[16], av[16];
    const ulonglong2* xp = reinterpret_cast<const ulonglong2*>(x + (size_t)n * 16);
    const ulonglong2* ap = reinterpret_cast<const ulonglong2*>(g_agg1 + (size_t)n * 16);
#pragma unroll
    for (int c = 0; c < 16; c++) { xv[c] = xp[c]; av[c] = ap[c]; }
    const ulonglong2* wl64 = reinterpret_cast<const ulonglong2*>(s_W);
    const ulonglong2* wr64 = reinterpret_cast<const ulonglong2*>(s_W + 1024);
    float* hp = reinterpret_cast<float*>(g_h) + (size_t)n * D_HID;
#pragma unroll 1
    for (int j = 0; j < D_HID; j++) {
        unsigned long long a0 = pack2(c_b1[j], 0.f);
        unsigned long long a1 = 0ull, a2 = 0ull, a3 = 0ull;
#pragma unroll
        for (int c = 0; c < 16; c++) {
            ulonglong2 wl = wl64[j * 16 + c];
            ulonglong2 wr = wr64[j * 16 + c];
            ffma2(a0, wl.x, av[c].x);
            ffma2(a1, wl.y, av[c].y);
            ffma2(a2, wr.x, xv[c].x);
            ffma2(a3, wr.y, xv[c].y);
        }
        float2 f0 = unpack2(a0), f1 = unpack2(a1), f2 = unpack2(a2), f3 = unpack2(a3);
        hp[j] = ((f0.x + f0.y) + (f1.x + f1.y)) + ((f2.x + f2.y) + (f3.x + f3.y));
    }
}

// ---------------- BN stats: vectorized float4 column sums ----------------
#define SROWS 512
__global__ __launch_bounds__(256) void k_colstats() {
    __shared__ float4 ssum[256];
    __shared__ float4 ssq[256];
    int j4 = threadIdx.x & 15;
    int rs = threadIdx.x >> 4;
    int row0 = blockIdx.x * SROWS;
    int rend = row0 + SROWS;
    if (rend > N_NODES) rend = N_NODES;
    float4 s = make_float4(0.f, 0.f, 0.f, 0.f);
    float4 q = make_float4(0.f, 0.f, 0.f, 0.f);
    for (int r = row0 + rs; r < rend; r += 16) {
        float4 v = g_h[(size_t)r * 16 + j4];
        s.x += v.x; s.y += v.y; s.z += v.z; s.w += v.w;
        q.x += v.x * v.x; q.y += v.y * v.y; q.z += v.z * v.z; q.w += v.w * v.w;
    }
    ssum[threadIdx.x] = s;
    ssq[threadIdx.x] = q;
    __syncthreads();
    for (int stride = 128; stride >= 16; stride >>= 1) {
        if (threadIdx.x < stride) {
            float4 a = ssum[threadIdx.x + stride];
            float4 b = ssq[threadIdx.x + stride];
            float4 sa = ssum[threadIdx.x];
            float4 sb = ssq[threadIdx.x];
            sa.x += a.x; sa.y += a.y; sa.z += a.z; sa.w += a.w;
            sb.x += b.x; sb.y += b.y; sb.z += b.z; sb.w += b.w;
            ssum[threadIdx.x] = sa;
            ssq[threadIdx.x] = sb;
        }
        __syncthreads();
    }
    if (threadIdx.x < 16) {
        float4 sa = ssum[threadIdx.x];
        float4 sb = ssq[threadIdx.x];
        int jb = threadIdx.x * 4;
        atomicAdd(&g_sum[jb + 0], sa.x);
        atomicAdd(&g_sum[jb + 1], sa.y);
        atomicAdd(&g_sum[jb + 2], sa.z);
        atomicAdd(&g_sum[jb + 3], sa.w);
        atomicAdd(&g_sumsq[jb + 0], sb.x);
        atomicAdd(&g_sumsq[jb + 1], sb.y);
        atomicAdd(&g_sumsq[jb + 2], sb.z);
        atomicAdd(&g_sumsq[jb + 3], sb.w);
    }
}

// ---- BN finalize + ReLU + both layer-2 projections (smem weights) ----
__global__ __launch_bounds__(256) void k_bnrelu_proj(float4* __restrict__ out,
                                                     const float* __restrict__ gamma,
                                                     const float* __restrict__ beta) {
    __shared__ float4 s_W2[1280];   // 20KB: W2l rows then W2r rows
    __shared__ float4 s_scale[16];
    __shared__ float4 s_shift[16];
#pragma unroll
    for (int t = 0; t < 5; t++) s_W2[threadIdx.x + t * 256] = g_W2[threadIdx.x + t * 256];
    if (threadIdx.x < D_HID) {
        int j = threadIdx.x;
        float mu = g_sum[j] * (1.0f / (float)N_NODES);
        float var = g_sumsq[j] * (1.0f / (float)N_NODES) - mu * mu;
        float rs = rsqrtf(var + BN_EPS);
        float sc = gamma[j] * rs;
        reinterpret_cast<float*>(s_scale)[j] = sc;
        reinterpret_cast<float*>(s_shift)[j] = beta[j] - mu * sc;
    }
    __syncthreads();
    int n = blockIdx.x * 256 + threadIdx.x;
    if (n >= N_NODES) return;
    float4 hv[16];
    const float4* hp = g_h + (size_t)n * 16;
#pragma unroll
    for (int c = 0; c < 16; c++) {
        float4 sc = s_scale[c];
        float4 sh = s_shift[c];
        float4 h = hp[c];
        h.x = fmaxf(fmaf(h.x, sc.x, sh.x), 0.f);
        h.y = fmaxf(fmaf(h.y, sc.y, sh.y), 0.f);
        h.z = fmaxf(fmaf(h.z, sc.z, sh.z), 0.f);
        h.w = fmaxf(fmaf(h.w, sc.w, sh.w), 0.f);
        hv[c] = h;
    }
    const ulonglong2* hv64 = reinterpret_cast<const ulonglong2*>(hv);
    const ulonglong2* wl64 = reinterpret_cast<const ulonglong2*>(s_W2);
    const ulonglong2* wr64 = reinterpret_cast<const ulonglong2*>(s_W2 + 640);
    float4* pp = g_p + (size_t)n * 10;
    float4* op = out + (size_t)n * 10;
    float pj[4], oj[4];
#pragma unroll 1
    for (int jb = 0; jb < 10; jb++) {
#pragma unroll
        for (int u = 0; u < 4; u++) {
            int j = jb * 4 + u;
            unsigned long long a0 = 0ull, a1 = 0ull;
            unsigned long long b0 = pack2(c_b2[j], 0.f), b1 = 0ull;
#pragma unroll
            for (int c = 0; c < 16; c++) {
                ulonglong2 wl = wl64[j * 16 + c];
                ulonglong2 wr = wr64[j * 16 + c];
                ffma2(a0, wl.x, hv64[c].x);
                ffma2(a1, wl.y, hv64[c].y);
                ffma2(b0, wr.x, hv64[c].x);
                ffma2(b1, wr.y, hv64[c].y);
            }
            float2 f0 = unpack2(a0), f1 = unpack2(a1);
            float2 g0 = unpack2(b0), g1 = unpack2(b1);
            pj[u] = (f0.x + f0.y) + (f1.x + f1.y);
            oj[u] = (g0.x + g0.y) + (g1.x + g1.y);
        }
        pp[jb] = make_float4(pj[0], pj[1], pj[2], pj[3]);
        op[jb] = make_float4(oj[0], oj[1], oj[2], oj[3]);
    }
}

// ------- aggregation 2: out[n] += mean of neighbor p (40-dim) -------
__global__ __launch_bounds__(256) void k_agg2(float4* __restrict__ out) {
    int gw = (blockIdx.x * blockDim.x + threadIdx.x) >> 5;
    int lane = threadIdx.x & 31;
    int sub = lane / 10;
    int q = lane - sub * 10;
    int n = gw * 3 + sub;
    if (sub >= 3 || n >= N_NODES) return;
    const int* row = g_adj + (size_t)n * ELL_W;
    int cnt = g_cnt[n];
    if (cnt > ELL_W) cnt = ELL_W;
    float4 acc = make_float4(0.f, 0.f, 0.f, 0.f);
    int i = 0;
    for (; i + 4 <= cnt; i += 4) {
        int4 s4 = *reinterpret_cast<const int4*>(row + i);
        float4 v0 = g_p[(size_t)s4.x * 10 + q];
        float4 v1 = g_p[(size_t)s4.y * 10 + q];
        float4 v2 = g_p[(size_t)s4.z * 10 + q];
        float4 v3 = g_p[(size_t)s4.w * 10 + q];
        acc.x += (v0.x + v1.x) + (v2.x + v3.x);
        acc.y += (v0.y + v1.y) + (v2.y + v3.y);
        acc.z += (v0.z + v1.z) + (v2.z + v3.z);
        acc.w += (v0.w + v1.w) + (v2.w + v3.w);
    }
    for (; i < cnt; i++) {
        int s = row[i];
        float4 v = g_p[(size_t)s * 10 + q];
        acc.x += v.x; acc.y += v.y; acc.z += v.z; acc.w += v.w;
    }
    float inv = 1.0f / (float)(cnt > 0 ? cnt : 1);
    float4 o = out[(size_t)n * 10 + q];
    o.x += acc.x * inv; o.y += acc.y * inv; o.z += acc.z * inv; o.w += acc.w * inv;
    out[(size_t)n * 10 + q] = o;
}

// ---------------- launch ----------------
extern "C" void kernel_launch(void* const* d_in, const int* in_sizes, int n_in,
                              void* d_out, int out_size) {
    const float4* x     = (const float4*)d_in[0];
    const int*    ei    = (const int*)d_in[1];   // int32 (jax x64 disabled)
    const float*  gamma = (const float*)d_in[5];
    const float*  beta  = (const float*)d_in[6];
    const int* src = ei;
    const int* dst = ei + E_EDGES;

    // Weight staging: W1l|W1r -> g_W1, W2l|W2r -> g_W2, biases -> constant
    cudaMemcpyToSymbolAsync(g_W1, d_in[2], D_HID * D_IN * sizeof(float), 0,     cudaMemcpyDeviceToDevice, 0);
    cudaMemcpyToSymbolAsync(g_W1, d_in[3], D_HID * D_IN * sizeof(float), 16384, cudaMemcpyDeviceToDevice, 0);
    cudaMemcpyToSymbolAsync(c_b1, d_in[4], D_HID * sizeof(float), 0,            cudaMemcpyDeviceToDevice, 0);
    cudaMemcpyToSymbolAsync(g_W2, d_in[7], D_OUT * D_HID * sizeof(float), 0,     cudaMemcpyDeviceToDevice, 0);
    cudaMemcpyToSymbolAsync(g_W2, d_in[8], D_OUT * D_HID * sizeof(float), 10240, cudaMemcpyDeviceToDevice, 0);
    cudaMemcpyToSymbolAsync(c_b2, d_in[9], D_OUT * sizeof(float), 0,             cudaMemcpyDeviceToDevice, 0);

    // ELL adjacency build (count + fill fused, shared by both layers)
    k_zero<<<256, 256>>>();
    k_countfill<<<(E_EDGES / 8 + 255) / 256, 256>>>(src, dst);

    // Layer 1
    k_agg1<<<(N_NODES / 2 + 7) / 8, 256>>>(x);
    k_gemm1<<<(N_NODES + 255) / 256, 256>>>(x);

    // BN stats + (finalize+ReLU+projections)
    k_colstats<<<(N_NODES + SROWS - 1) / SROWS, 256>>>();
    k_bnrelu_proj<<<(N_NODES + 255) / 256, 256>>>((float4*)d_out, gamma, beta);

    // Layer 2: add neighbor-mean of p into out
    k_agg2<<<(N_NODES / 3 + 8) / 8, 256>>>((float4*)d_out);
}